// round 11
// baseline (speedup 1.0000x reference)
#include <cuda_runtime.h>
#include <cstdint>

// Problem constants (match reference)
#define FEAT_W   32
#define FEAT_H   32
#define HW       1024          // 32*32
#define M_GT     64
#define GT_STRIDE 14

// Output tensor offsets in floats. BN = 4096; slab = BN*HW floats.
#define SLAB     4194304ll
#define OFF_CLS   (0ll)
#define OFF_CLSW  (SLAB*1)
#define OFF_R2    (SLAB*2)
#define OFF_R2W   (SLAB*4)
#define OFF_R3    (SLAB*6)
#define OFF_R3W   (SLAB*8)
#define OFF_DL    (SLAB*10)
#define OFF_DLW   (SLAB*11)
#define OFF_DIM   (SLAB*12)
#define OFF_DIMW  (SLAB*15)
#define OFF_ROT   (SLAB*18)
#define OFF_ROTW  (SLAB*19)

// Default write-back store (best measured policy, R8/R10).
__device__ __forceinline__ void st4(float* p, float a, float b, float c, float d) {
    float4 v = make_float4(a, b, c, d);
    *reinterpret_cast<float4*>(p) = v;
}

// TWO adjacent boxes per 512-thread CTA: boxes 2k and 2k+1 write adjacent 4 KB
// regions of every channel, so each CTA issues 8 KB contiguous bursts per
// channel from one SM. (R9: 2 KB bursts -> HBM 3.9 TB/s; 4 KB -> 5.55 TB/s;
// this probes 8 KB.) Warps 0-7 own box A, warps 8-15 box B; warps/SM unchanged.
__global__ __launch_bounds__(512, 4)
void rcnn3d_label_kernel(const float* __restrict__ boxes,
                         const float* __restrict__ gt_boxes,
                         const int*   __restrict__ match_pos_flag,
                         const int*   __restrict__ match_gt_id,
                         float*       __restrict__ out)
{
    const int h   = threadIdx.x >> 8;              // 0/1: which box in the pair
    const int tid = threadIdx.x & 255;             // 0..255 within the box
    const int bn  = (blockIdx.x << 1) + h;         // box id 0..4095
    const int b   = bn >> 10;

    __shared__ __align__(16) float exs[2][FEAT_W];
    __shared__ __align__(16) float eys[2][FEAT_H];

    // ---- per-box scalars (uniform within each half; broadcast loads) ----
    const float x1 = __ldg(boxes + (size_t)bn * 4 + 0);
    const float y1 = __ldg(boxes + (size_t)bn * 4 + 1);
    const float x2 = __ldg(boxes + (size_t)bn * 4 + 2);
    const float y2 = __ldg(boxes + (size_t)bn * 4 + 3);
    const int gid  = __ldg(match_gt_id + bn);
    const int flag = __ldg(match_pos_flag + bn);

    const float* g = gt_boxes + ((size_t)b * M_GT + gid) * GT_STRIDE;
    const float kxg   = __ldg(g + 4);
    const float kyg   = __ldg(g + 5);
    const float vis   = __ldg(g + 6);
    const float dim0  = __ldg(g + 7);
    const float dim1  = __ldg(g + 8);
    const float dim2  = __ldg(g + 9);
    const float depth = __ldg(g + 12);
    const float rot   = __ldg(g + 13);

    const float cx = 0.5f * (x1 + x2);
    const float cy = 0.5f * (y1 + y2);
    const float hw = 0.5f * (x2 - x1) * 1.2f;   // EXPAND
    const float hh = 0.5f * (y2 - y1) * 1.2f;
    const float ex1 = cx - hw, ex2 = cx + hw;
    const float ey1 = cy - hh, ey2 = cy + hh;
    const float sx = (float)FEAT_W / (ex2 - ex1 + 1.0f);
    const float sy = (float)FEAT_H / (ey2 - ey1 + 1.0f);
    const float kx = (kxg - ex1) * sx;
    const float ky = (kyg - ey1) * sy;
    const bool valid = (vis != 0.0f) && (flag > 0);

    // ---- separable Gaussian tables: 64 expf per box (128 per CTA) ----
    if (tid < FEAT_W) {
        const float d = (float)tid + 0.5f - kx;
        exs[h][tid] = expf(-(d * d) / 5.12f);    // 2*SIGMA^2
    } else if (tid < FEAT_W + FEAT_H) {
        const int r = tid - FEAT_W;
        const float d = (float)r + 0.5f - ky;
        eys[h][r] = expf(-(d * d) / 5.12f);
    }
    __syncthreads();

    // ---- analytic 'has': peak of exs[gx]*eys[gy] at clamped-nearest cell ----
    int ixn = __float2int_rn(kx - 0.5f); ixn = min(FEAT_W - 1, max(0, ixn));
    int iyn = __float2int_rn(ky - 0.5f); iyn = min(FEAT_H - 1, max(0, iyn));
    const float smax = exs[h][ixn] * eys[h][iyn];
    const bool  has  = valid && (smax >= 0.6f);
    const float hasf = has ? 1.0f : 0.0f;

    // ---- this thread's 4 pixels: row gy, cols gx0..gx0+3 ----
    const int gy  = tid >> 3;
    const int gx0 = (tid & 7) << 2;
    const float ey   = eys[h][gy];
    const float offy = ky - (float)gy;
    const float4 exv = reinterpret_cast<const float4*>(exs[h])[tid & 7];
    const float exa[4] = {exv.x, exv.y, exv.z, exv.w};

    float cls[4], offx[4], m2f[4], m3f[4];
#pragma unroll
    for (int j = 0; j < 4; ++j) {
        const float gx = (float)(gx0 + j);
        const float sc = exa[j] * ey;
        offx[j] = kx - gx;
        m2f[j] = (valid && sc >= 0.6f) ? 1.0f : 0.0f;
        m3f[j] = (valid && sc >= 0.5f) ? 1.0f : 0.0f;   // depth thr == 3d thr
        cls[j] = has ? sc : -1.0f;                      // branchless
    }

    // ---- 20 coalesced float4 stores, default .wb policy ----
    const long long pix  = (long long)tid * 4;
    const long long base = (long long)bn * HW + pix;
    const long long b2c  = (long long)bn * 2 * HW + pix;
    const long long b3c  = (long long)bn * 3 * HW + pix;

    st4(out + OFF_CLS  + base, cls[0], cls[1], cls[2], cls[3]);
    st4(out + OFF_CLSW + base, hasf, hasf, hasf, hasf);

    st4(out + OFF_R2  + b2c,      offx[0]*m2f[0], offx[1]*m2f[1], offx[2]*m2f[2], offx[3]*m2f[3]);
    st4(out + OFF_R2  + b2c + HW, offy*m2f[0],    offy*m2f[1],    offy*m2f[2],    offy*m2f[3]);
    st4(out + OFF_R2W + b2c,      m2f[0], m2f[1], m2f[2], m2f[3]);
    st4(out + OFF_R2W + b2c + HW, m2f[0], m2f[1], m2f[2], m2f[3]);

    st4(out + OFF_R3  + b2c,      offx[0]*m3f[0], offx[1]*m3f[1], offx[2]*m3f[2], offx[3]*m3f[3]);
    st4(out + OFF_R3  + b2c + HW, offy*m3f[0],    offy*m3f[1],    offy*m3f[2],    offy*m3f[3]);
    st4(out + OFF_R3W + b2c,      m3f[0], m3f[1], m3f[2], m3f[3]);
    st4(out + OFF_R3W + b2c + HW, m3f[0], m3f[1], m3f[2], m3f[3]);

    st4(out + OFF_DL  + base, depth*m3f[0], depth*m3f[1], depth*m3f[2], depth*m3f[3]);
    st4(out + OFF_DLW + base, m3f[0], m3f[1], m3f[2], m3f[3]);

    st4(out + OFF_DIM  + b3c,        dim0*m3f[0], dim0*m3f[1], dim0*m3f[2], dim0*m3f[3]);
    st4(out + OFF_DIM  + b3c + HW,   dim1*m3f[0], dim1*m3f[1], dim1*m3f[2], dim1*m3f[3]);
    st4(out + OFF_DIM  + b3c + 2*HW, dim2*m3f[0], dim2*m3f[1], dim2*m3f[2], dim2*m3f[3]);
    st4(out + OFF_DIMW + b3c,        m3f[0], m3f[1], m3f[2], m3f[3]);
    st4(out + OFF_DIMW + b3c + HW,   m3f[0], m3f[1], m3f[2], m3f[3]);
    st4(out + OFF_DIMW + b3c + 2*HW, m3f[0], m3f[1], m3f[2], m3f[3]);

    st4(out + OFF_ROT  + base, rot*m3f[0], rot*m3f[1], rot*m3f[2], rot*m3f[3]);
    st4(out + OFF_ROTW + base, m3f[0], m3f[1], m3f[2], m3f[3]);
}

extern "C" void kernel_launch(void* const* d_in, const int* in_sizes, int n_in,
                              void* d_out, int out_size) {
    const float* boxes          = (const float*)d_in[0];
    const float* gt_boxes       = (const float*)d_in[1];
    const int*   match_pos_flag = (const int*)d_in[2];
    const int*   match_gt_id    = (const int*)d_in[3];
    float* out = (float*)d_out;

    // 2048 CTAs x 512 threads: one CTA per adjacent box pair, 8 KB contiguous
    // burst per channel per CTA, 64 warps/SM unchanged.
    rcnn3d_label_kernel<<<2048, 512>>>(boxes, gt_boxes, match_pos_flag,
                                       match_gt_id, out);
}

// round 12
// speedup vs baseline: 1.0132x; 1.0132x over previous
#include <cuda_runtime.h>
#include <cstdint>

// ============================================================================
// RCNN3DLabelFromMatch — final kernel (R10 config, measured optimum).
//
// Roofline summary (11 rounds of evidence):
//   - Pure store-bound problem: 335.5 MB dense output per replay, ~16 KB input.
//   - This config: 49.7 us ncu, SM->L2 6.75 TB/s (~97% of the ~6300 B/cyc LTS
//     chip cap), HBM writes 5.56 TB/s.
//   - Falsified levers: MUFU reduction (neutral), TMA bulk path (neutral),
//     L2 evict_last pinning (inert without carveout), v8 256-bit stores
//     (neutral-worse), 2 KB bursts (-29% HBM rate), 8 KB bursts (-8%).
//   - Optimum: one 256-thread CTA per box, 4 KB contiguous burst per channel,
//     default .wb stores, separable-exp tables in SMEM, branchless epilogue.
// ============================================================================

#define FEAT_W   32
#define FEAT_H   32
#define HW       1024          // 32*32
#define M_GT     64
#define GT_STRIDE 14

// Output tensor offsets in floats. BN = 4096; slab = BN*HW floats.
#define SLAB     4194304ll
#define OFF_CLS   (0ll)
#define OFF_CLSW  (SLAB*1)
#define OFF_R2    (SLAB*2)
#define OFF_R2W   (SLAB*4)
#define OFF_R3    (SLAB*6)
#define OFF_R3W   (SLAB*8)
#define OFF_DL    (SLAB*10)
#define OFF_DLW   (SLAB*11)
#define OFF_DIM   (SLAB*12)
#define OFF_DIMW  (SLAB*15)
#define OFF_ROT   (SLAB*18)
#define OFF_ROTW  (SLAB*19)

// Default write-back store: best measured policy. Dirty lines keep normal L2
// priority; lines still resident at the next graph replay are overwritten in
// L2 without costing a DRAM writeback.
__device__ __forceinline__ void st4(float* p, float a, float b, float c, float d) {
    float4 v = make_float4(a, b, c, d);
    *reinterpret_cast<float4*>(p) = v;
}

__global__ __launch_bounds__(256, 8)
void rcnn3d_label_kernel(const float* __restrict__ boxes,
                         const float* __restrict__ gt_boxes,
                         const int*   __restrict__ match_pos_flag,
                         const int*   __restrict__ match_gt_id,
                         float*       __restrict__ out)
{
    const int bn  = blockIdx.x;            // b*N + n
    const int b   = bn >> 10;
    const int tid = threadIdx.x;

    __shared__ __align__(16) float exs[FEAT_W];
    __shared__ __align__(16) float eys[FEAT_H];

    // ---- per-box scalars (uniform; broadcast loads) ----
    const float x1 = __ldg(boxes + (size_t)bn * 4 + 0);
    const float y1 = __ldg(boxes + (size_t)bn * 4 + 1);
    const float x2 = __ldg(boxes + (size_t)bn * 4 + 2);
    const float y2 = __ldg(boxes + (size_t)bn * 4 + 3);
    const int gid  = __ldg(match_gt_id + bn);
    const int flag = __ldg(match_pos_flag + bn);

    const float* g = gt_boxes + ((size_t)b * M_GT + gid) * GT_STRIDE;
    const float kxg   = __ldg(g + 4);
    const float kyg   = __ldg(g + 5);
    const float vis   = __ldg(g + 6);
    const float dim0  = __ldg(g + 7);
    const float dim1  = __ldg(g + 8);
    const float dim2  = __ldg(g + 9);
    const float depth = __ldg(g + 12);
    const float rot   = __ldg(g + 13);

    const float cx = 0.5f * (x1 + x2);
    const float cy = 0.5f * (y1 + y2);
    const float hw = 0.5f * (x2 - x1) * 1.2f;   // EXPAND
    const float hh = 0.5f * (y2 - y1) * 1.2f;
    const float ex1 = cx - hw, ex2 = cx + hw;
    const float ey1 = cy - hh, ey2 = cy + hh;
    const float sx = (float)FEAT_W / (ex2 - ex1 + 1.0f);
    const float sy = (float)FEAT_H / (ey2 - ey1 + 1.0f);
    const float kx = (kxg - ex1) * sx;
    const float ky = (kyg - ey1) * sy;
    const bool valid = (vis != 0.0f) && (flag > 0);

    // ---- separable Gaussian tables: 64 expf per CTA (16x fewer than naive) ----
    if (tid < FEAT_W) {
        const float d = (float)tid + 0.5f - kx;
        exs[tid] = expf(-(d * d) / 5.12f);       // 2*SIGMA^2
    } else if (tid < FEAT_W + FEAT_H) {
        const int r = tid - FEAT_W;
        const float d = (float)r + 0.5f - ky;
        eys[r] = expf(-(d * d) / 5.12f);
    }
    __syncthreads();

    // ---- analytic 'has': peak of exs[gx]*eys[gy] at clamped-nearest cell ----
    int ixn = __float2int_rn(kx - 0.5f); ixn = min(FEAT_W - 1, max(0, ixn));
    int iyn = __float2int_rn(ky - 0.5f); iyn = min(FEAT_H - 1, max(0, iyn));
    const float smax = exs[ixn] * eys[iyn];
    const bool  has  = valid && (smax >= 0.6f);
    const float hasf = has ? 1.0f : 0.0f;

    // ---- this thread's 4 pixels: row gy, cols gx0..gx0+3 ----
    const int gy  = tid >> 3;
    const int gx0 = (tid & 7) << 2;
    const float ey   = eys[gy];
    const float offy = ky - (float)gy;
    const float4 exv = reinterpret_cast<const float4*>(exs)[tid & 7];
    const float exa[4] = {exv.x, exv.y, exv.z, exv.w};

    float cls[4], offx[4], m2f[4], m3f[4];
#pragma unroll
    for (int j = 0; j < 4; ++j) {
        const float gx = (float)(gx0 + j);
        const float sc = exa[j] * ey;
        offx[j] = kx - gx;
        m2f[j] = (valid && sc >= 0.6f) ? 1.0f : 0.0f;
        m3f[j] = (valid && sc >= 0.5f) ? 1.0f : 0.0f;   // depth thr == 3d thr
        cls[j] = has ? sc : -1.0f;                      // branchless (SELP)
    }

    // ---- 20 coalesced float4 stores, default .wb policy ----
    const long long pix  = (long long)tid * 4;
    const long long base = (long long)bn * HW + pix;
    const long long b2c  = (long long)bn * 2 * HW + pix;
    const long long b3c  = (long long)bn * 3 * HW + pix;

    st4(out + OFF_CLS  + base, cls[0], cls[1], cls[2], cls[3]);
    st4(out + OFF_CLSW + base, hasf, hasf, hasf, hasf);

    st4(out + OFF_R2  + b2c,      offx[0]*m2f[0], offx[1]*m2f[1], offx[2]*m2f[2], offx[3]*m2f[3]);
    st4(out + OFF_R2  + b2c + HW, offy*m2f[0],    offy*m2f[1],    offy*m2f[2],    offy*m2f[3]);
    st4(out + OFF_R2W + b2c,      m2f[0], m2f[1], m2f[2], m2f[3]);
    st4(out + OFF_R2W + b2c + HW, m2f[0], m2f[1], m2f[2], m2f[3]);

    st4(out + OFF_R3  + b2c,      offx[0]*m3f[0], offx[1]*m3f[1], offx[2]*m3f[2], offx[3]*m3f[3]);
    st4(out + OFF_R3  + b2c + HW, offy*m3f[0],    offy*m3f[1],    offy*m3f[2],    offy*m3f[3]);
    st4(out + OFF_R3W + b2c,      m3f[0], m3f[1], m3f[2], m3f[3]);
    st4(out + OFF_R3W + b2c + HW, m3f[0], m3f[1], m3f[2], m3f[3]);

    st4(out + OFF_DL  + base, depth*m3f[0], depth*m3f[1], depth*m3f[2], depth*m3f[3]);
    st4(out + OFF_DLW + base, m3f[0], m3f[1], m3f[2], m3f[3]);

    st4(out + OFF_DIM  + b3c,        dim0*m3f[0], dim0*m3f[1], dim0*m3f[2], dim0*m3f[3]);
    st4(out + OFF_DIM  + b3c + HW,   dim1*m3f[0], dim1*m3f[1], dim1*m3f[2], dim1*m3f[3]);
    st4(out + OFF_DIM  + b3c + 2*HW, dim2*m3f[0], dim2*m3f[1], dim2*m3f[2], dim2*m3f[3]);
    st4(out + OFF_DIMW + b3c,        m3f[0], m3f[1], m3f[2], m3f[3]);
    st4(out + OFF_DIMW + b3c + HW,   m3f[0], m3f[1], m3f[2], m3f[3]);
    st4(out + OFF_DIMW + b3c + 2*HW, m3f[0], m3f[1], m3f[2], m3f[3]);

    st4(out + OFF_ROT  + base, rot*m3f[0], rot*m3f[1], rot*m3f[2], rot*m3f[3]);
    st4(out + OFF_ROTW + base, m3f[0], m3f[1], m3f[2], m3f[3]);
}

extern "C" void kernel_launch(void* const* d_in, const int* in_sizes, int n_in,
                              void* d_out, int out_size) {
    const float* boxes          = (const float*)d_in[0];
    const float* gt_boxes       = (const float*)d_in[1];
    const int*   match_pos_flag = (const int*)d_in[2];
    const int*   match_gt_id    = (const int*)d_in[3];
    float* out = (float*)d_out;

    // One 256-thread CTA per box (measured optimum): 4096 CTAs, 4 KB
    // contiguous burst per channel per CTA, default .wb stores.
    rcnn3d_label_kernel<<<4096, 256>>>(boxes, gt_boxes, match_pos_flag,
                                       match_gt_id, out);
}

// round 13
// speedup vs baseline: 1.0150x; 1.0018x over previous
#include <cuda_runtime.h>
#include <cstdint>

// ============================================================================
// Channel-major decomposition: each CTA writes one contiguous 64-96 KB window
// of a SINGLE output tensor as a sequential stream (vs. box-major's 20-way
// interleaved 4 KB bursts). Probes DRAM row-locality / L2 sector packing.
// ============================================================================

#define FEAT_W   32
#define FEAT_H   32
#define HW       1024
#define M_GT     64
#define GT_STRIDE 14
#define TWO_SIG2 5.12f

#define SLAB     4194304ll
#define OFF_CLS   (0ll)
#define OFF_CLSW  (SLAB*1)
#define OFF_R2    (SLAB*2)
#define OFF_R2W   (SLAB*4)
#define OFF_R3    (SLAB*6)
#define OFF_R3W   (SLAB*8)
#define OFF_DL    (SLAB*10)
#define OFF_DLW   (SLAB*11)
#define OFF_DIM   (SLAB*12)
#define OFF_DIMW  (SLAB*15)
#define OFF_ROT   (SLAB*18)
#define OFF_ROTW  (SLAB*19)

__device__ __forceinline__ void st4(float* p, float a, float b, float c, float d) {
    float4 v = make_float4(a, b, c, d);
    *reinterpret_cast<float4*>(p) = v;
}

// Grid: 4608 CTAs.
//  type 0 cls   [0,256)     C=1 G=16   type 1 clsw  [256,512)
//  type 2 r2    [512,1024)  C=2 G=8    type 3 r2w   [1024,1536)
//  type 4 r3    [1536,2048) C=2 G=8    type 5 r3w   [2048,2560)
//  type 6 dl    [2560,2816) C=1 G=16   type 7 dlw   [2816,3072)
//  type 8 dim   [3072,3584) C=3 G=8    type 9 dimw  [3584,4096)
//  type 10 rot  [4096,4352) C=1 G=16   type 11 rotw [4352,4608)
__global__ __launch_bounds__(256, 8)
void rcnn3d_label_kernel(const float* __restrict__ boxes,
                         const float* __restrict__ gt_boxes,
                         const int*   __restrict__ match_pos_flag,
                         const int*   __restrict__ match_gt_id,
                         float*       __restrict__ out)
{
    __shared__ __align__(16) float s_ex[16][FEAT_W];
    __shared__ __align__(16) float s_ey[16][FEAT_H];
    __shared__ float s_kx[16], s_ky[16], s_hasf[16], s_validf[16];
    __shared__ float s_aux[16][8];   // [0..2]=dims, [3]=depth, [4]=rot

    const int bid = blockIdx.x;
    const int tid = threadIdx.x;

    int type, start, C, G;
    long long toff;
    if (bid < 512) {
        if (bid < 256)       { type = 0;  start = 0;    C = 1; G = 16; toff = OFF_CLS;  }
        else                 { type = 1;  start = 256;  C = 1; G = 16; toff = OFF_CLSW; }
    } else if (bid < 2560) {
        if (bid < 1024)      { type = 2;  start = 512;  C = 2; G = 8;  toff = OFF_R2;   }
        else if (bid < 1536) { type = 3;  start = 1024; C = 2; G = 8;  toff = OFF_R2W;  }
        else if (bid < 2048) { type = 4;  start = 1536; C = 2; G = 8;  toff = OFF_R3;   }
        else                 { type = 5;  start = 2048; C = 2; G = 8;  toff = OFF_R3W;  }
    } else if (bid < 3072) {
        if (bid < 2816)      { type = 6;  start = 2560; C = 1; G = 16; toff = OFF_DL;   }
        else                 { type = 7;  start = 2816; C = 1; G = 16; toff = OFF_DLW;  }
    } else if (bid < 4096) {
        if (bid < 3584)      { type = 8;  start = 3072; C = 3; G = 8;  toff = OFF_DIM;  }
        else                 { type = 9;  start = 3584; C = 3; G = 8;  toff = OFF_DIMW; }
    } else {
        if (bid < 4352)      { type = 10; start = 4096; C = 1; G = 16; toff = OFF_ROT;  }
        else                 { type = 11; start = 4352; C = 1; G = 16; toff = OFF_ROTW; }
    }
    const int bn0 = (bid - start) * G;

    // ---- phase 1: per-box scalars (threads 0..G-1, one box each) ----
    if (tid < G) {
        const int bn = bn0 + tid;
        const int b  = bn >> 10;
        const float x1 = __ldg(boxes + (size_t)bn * 4 + 0);
        const float y1 = __ldg(boxes + (size_t)bn * 4 + 1);
        const float x2 = __ldg(boxes + (size_t)bn * 4 + 2);
        const float y2 = __ldg(boxes + (size_t)bn * 4 + 3);
        const int gid  = __ldg(match_gt_id + bn);
        const int flag = __ldg(match_pos_flag + bn);

        const float* g = gt_boxes + ((size_t)b * M_GT + gid) * GT_STRIDE;
        const float kxg = __ldg(g + 4);
        const float kyg = __ldg(g + 5);
        const float vis = __ldg(g + 6);

        const float cx = 0.5f * (x1 + x2);
        const float cy = 0.5f * (y1 + y2);
        const float hw = 0.5f * (x2 - x1) * 1.2f;   // EXPAND
        const float hh = 0.5f * (y2 - y1) * 1.2f;
        const float ex1 = cx - hw, ex2 = cx + hw;
        const float ey1 = cy - hh, ey2 = cy + hh;
        const float sx = (float)FEAT_W / (ex2 - ex1 + 1.0f);
        const float sy = (float)FEAT_H / (ey2 - ey1 + 1.0f);
        const float kx = (kxg - ex1) * sx;
        const float ky = (kyg - ey1) * sy;
        const bool valid = (vis != 0.0f) && (flag > 0);

        // analytic has: same FP expression as the table entries -> identical bits
        int ixn = __float2int_rn(kx - 0.5f); ixn = min(FEAT_W - 1, max(0, ixn));
        int iyn = __float2int_rn(ky - 0.5f); iyn = min(FEAT_H - 1, max(0, iyn));
        const float dxm = (float)ixn + 0.5f - kx;
        const float dym = (float)iyn + 0.5f - ky;
        const float smax = expf(-(dxm * dxm) / TWO_SIG2) * expf(-(dym * dym) / TWO_SIG2);

        s_kx[tid] = kx;
        s_ky[tid] = ky;
        s_validf[tid] = valid ? 1.0f : 0.0f;
        s_hasf[tid]   = (valid && smax >= 0.6f) ? 1.0f : 0.0f;
        s_aux[tid][0] = __ldg(g + 7);
        s_aux[tid][1] = __ldg(g + 8);
        s_aux[tid][2] = __ldg(g + 9);
        s_aux[tid][3] = __ldg(g + 12);
        s_aux[tid][4] = __ldg(g + 13);
    }
    __syncthreads();

    // ---- phase 2: separable exp tables for G boxes (G*64 expf per CTA) ----
    for (int e = tid; e < G * 64; e += 256) {
        const int k  = e >> 6;
        const int p  = e & 63;
        const int pp = p & 31;
        const float c = (p < 32) ? s_kx[k] : s_ky[k];
        const float d = (float)pp + 0.5f - c;
        const float v = expf(-(d * d) / TWO_SIG2);
        if (p < 32) s_ex[k][pp] = v; else s_ey[k][pp] = v;
    }
    __syncthreads();

    // ---- phase 3: sequential store stream over this CTA's window ----
    const int gy  = tid >> 3;
    const int gx0 = (tid & 7) << 2;
    float* outp = out + toff + (long long)bn0 * C * HW + (long long)tid * 4;

    if (type == 0) {            // cls: has ? score : -1
#pragma unroll
        for (int k = 0; k < 16; ++k) {
            const float ey = s_ey[k][gy];
            const float4 e4 = reinterpret_cast<const float4*>(s_ex[k])[tid & 7];
            const bool has = s_hasf[k] != 0.0f;
            st4(outp + k * HW,
                has ? e4.x * ey : -1.0f, has ? e4.y * ey : -1.0f,
                has ? e4.z * ey : -1.0f, has ? e4.w * ey : -1.0f);
        }
    } else if (type == 1) {     // clsw: constant hasf per box
#pragma unroll
        for (int k = 0; k < 16; ++k) {
            const float h = s_hasf[k];
            st4(outp + k * HW, h, h, h, h);
        }
    } else if (type == 2 || type == 4) {   // reg_2d / reg_3d (offx, offy)
        const float thr = (type == 2) ? 0.6f : 0.5f;
#pragma unroll
        for (int k = 0; k < 8; ++k) {
            const float kx = s_kx[k];
            const float ey = s_ey[k][gy];
            const float4 e4 = reinterpret_cast<const float4*>(s_ex[k])[tid & 7];
            const float vf = s_validf[k];
            const float offy = s_ky[k] - (float)gy;
            const float ex[4] = {e4.x, e4.y, e4.z, e4.w};
            float m[4], vx[4];
#pragma unroll
            for (int j = 0; j < 4; ++j) {
                const float sc = ex[j] * ey;
                m[j]  = (sc >= thr ? 1.0f : 0.0f) * vf;
                vx[j] = (kx - (float)(gx0 + j)) * m[j];
            }
            st4(outp + k * 2 * HW,      vx[0], vx[1], vx[2], vx[3]);
            st4(outp + k * 2 * HW + HW, offy * m[0], offy * m[1], offy * m[2], offy * m[3]);
        }
    } else if (type == 3 || type == 5) {   // reg_2d_w / reg_3d_w (mask x2)
        const float thr = (type == 3) ? 0.6f : 0.5f;
#pragma unroll
        for (int k = 0; k < 8; ++k) {
            const float ey = s_ey[k][gy];
            const float4 e4 = reinterpret_cast<const float4*>(s_ex[k])[tid & 7];
            const float vf = s_validf[k];
            const float ex[4] = {e4.x, e4.y, e4.z, e4.w};
            float m[4];
#pragma unroll
            for (int j = 0; j < 4; ++j)
                m[j] = (ex[j] * ey >= thr ? 1.0f : 0.0f) * vf;
            st4(outp + k * 2 * HW,      m[0], m[1], m[2], m[3]);
            st4(outp + k * 2 * HW + HW, m[0], m[1], m[2], m[3]);
        }
    } else if (type == 8 || type == 9) {   // dim_label / dim_label_w (C=3)
#pragma unroll
        for (int k = 0; k < 8; ++k) {
            const float ey = s_ey[k][gy];
            const float4 e4 = reinterpret_cast<const float4*>(s_ex[k])[tid & 7];
            const float vf = s_validf[k];
            const float ex[4] = {e4.x, e4.y, e4.z, e4.w};
            const float d0 = (type == 8) ? s_aux[k][0] : 1.0f;
            const float d1 = (type == 8) ? s_aux[k][1] : 1.0f;
            const float d2 = (type == 8) ? s_aux[k][2] : 1.0f;
            float m[4];
#pragma unroll
            for (int j = 0; j < 4; ++j)
                m[j] = (ex[j] * ey >= 0.5f ? 1.0f : 0.0f) * vf;
            st4(outp + k * 3 * HW,          d0 * m[0], d0 * m[1], d0 * m[2], d0 * m[3]);
            st4(outp + k * 3 * HW + HW,     d1 * m[0], d1 * m[1], d1 * m[2], d1 * m[3]);
            st4(outp + k * 3 * HW + 2 * HW, d2 * m[0], d2 * m[1], d2 * m[2], d2 * m[3]);
        }
    } else {                    // types 6/7/10/11: C=1, m3-based (dl/dlw/rot/rotw)
#pragma unroll
        for (int k = 0; k < 16; ++k) {
            const float ey = s_ey[k][gy];
            const float4 e4 = reinterpret_cast<const float4*>(s_ex[k])[tid & 7];
            const float vf = s_validf[k];
            const float ex[4] = {e4.x, e4.y, e4.z, e4.w};
            float s;
            if (type == 6)       s = s_aux[k][3];   // depth
            else if (type == 10) s = s_aux[k][4];   // rot
            else                 s = 1.0f;          // weights
            float m[4];
#pragma unroll
            for (int j = 0; j < 4; ++j)
                m[j] = (ex[j] * ey >= 0.5f ? 1.0f : 0.0f) * vf;
            st4(outp + k * HW, s * m[0], s * m[1], s * m[2], s * m[3]);
        }
    }
}

extern "C" void kernel_launch(void* const* d_in, const int* in_sizes, int n_in,
                              void* d_out, int out_size) {
    const float* boxes          = (const float*)d_in[0];
    const float* gt_boxes       = (const float*)d_in[1];
    const int*   match_pos_flag = (const int*)d_in[2];
    const int*   match_gt_id    = (const int*)d_in[3];
    float* out = (float*)d_out;

    // 4608 CTAs x 256 threads: each CTA streams one contiguous 64-96 KB window
    // of a single output tensor (channel-major; probes DRAM write locality).
    rcnn3d_label_kernel<<<4608, 256>>>(boxes, gt_boxes, match_pos_flag,
                                       match_gt_id, out);
}

// round 14
// speedup vs baseline: 1.0274x; 1.0122x over previous
#include <cuda_runtime.h>
#include <cstdint>

// ============================================================================
// RCNN3DLabelFromMatch — FINAL kernel (measured optimum over 13 variants).
//
// Problem shape: pure store-bound. 335.5 MB dense output per replay (irreducible
// — 12 dense tensors, harness poisons d_out), ~16 KB hot input.
//
// Measured roofline on GB300 (sm_103a):
//   SM->L2 ~6.7 TB/s (~97% of the ~6300 B/cyc LTS chip cap), HBM writes
//   ~5.5 TB/s, ncu dur 49.7-50.6 us across ALL viable configurations.
// Falsified levers: MUFU reduction (neutral), TMA bulk path alone/hybrid
//   (neutral), L2 evict_last (inert w/o carveout), .cs vs .wb (wb marginally
//   best), v8 256-bit stores (neutral-worse), 2 KB bursts (-29% HBM rate),
//   8 KB bursts (-8%), channel-major sequential streams (neutral).
// Optimum: one 256-thread CTA per box, 20 coalesced STG.128 per thread with
//   4 KB contiguous burst per channel per CTA, default .wb, separable-exp
//   tables (64 expf/CTA) in SMEM, analytic 'has', branchless epilogue.
// ============================================================================

#define FEAT_W   32
#define FEAT_H   32
#define HW       1024          // 32*32
#define M_GT     64
#define GT_STRIDE 14

// Output tensor offsets in floats. BN = 4096; slab = BN*HW floats.
#define SLAB     4194304ll
#define OFF_CLS   (0ll)
#define OFF_CLSW  (SLAB*1)
#define OFF_R2    (SLAB*2)
#define OFF_R2W   (SLAB*4)
#define OFF_R3    (SLAB*6)
#define OFF_R3W   (SLAB*8)
#define OFF_DL    (SLAB*10)
#define OFF_DLW   (SLAB*11)
#define OFF_DIM   (SLAB*12)
#define OFF_DIMW  (SLAB*15)
#define OFF_ROT   (SLAB*18)
#define OFF_ROTW  (SLAB*19)

// Default write-back store: best measured policy. Dirty lines keep normal L2
// priority; lines still resident at the next graph replay are overwritten in
// L2 without costing a DRAM writeback.
__device__ __forceinline__ void st4(float* p, float a, float b, float c, float d) {
    float4 v = make_float4(a, b, c, d);
    *reinterpret_cast<float4*>(p) = v;
}

__global__ __launch_bounds__(256, 8)
void rcnn3d_label_kernel(const float* __restrict__ boxes,
                         const float* __restrict__ gt_boxes,
                         const int*   __restrict__ match_pos_flag,
                         const int*   __restrict__ match_gt_id,
                         float*       __restrict__ out)
{
    const int bn  = blockIdx.x;            // b*N + n
    const int b   = bn >> 10;
    const int tid = threadIdx.x;

    __shared__ __align__(16) float exs[FEAT_W];
    __shared__ __align__(16) float eys[FEAT_H];

    // ---- per-box scalars (uniform; broadcast loads) ----
    const float x1 = __ldg(boxes + (size_t)bn * 4 + 0);
    const float y1 = __ldg(boxes + (size_t)bn * 4 + 1);
    const float x2 = __ldg(boxes + (size_t)bn * 4 + 2);
    const float y2 = __ldg(boxes + (size_t)bn * 4 + 3);
    const int gid  = __ldg(match_gt_id + bn);
    const int flag = __ldg(match_pos_flag + bn);

    const float* g = gt_boxes + ((size_t)b * M_GT + gid) * GT_STRIDE;
    const float kxg   = __ldg(g + 4);
    const float kyg   = __ldg(g + 5);
    const float vis   = __ldg(g + 6);
    const float dim0  = __ldg(g + 7);
    const float dim1  = __ldg(g + 8);
    const float dim2  = __ldg(g + 9);
    const float depth = __ldg(g + 12);
    const float rot   = __ldg(g + 13);

    const float cx = 0.5f * (x1 + x2);
    const float cy = 0.5f * (y1 + y2);
    const float hw = 0.5f * (x2 - x1) * 1.2f;   // EXPAND
    const float hh = 0.5f * (y2 - y1) * 1.2f;
    const float ex1 = cx - hw, ex2 = cx + hw;
    const float ey1 = cy - hh, ey2 = cy + hh;
    const float sx = (float)FEAT_W / (ex2 - ex1 + 1.0f);
    const float sy = (float)FEAT_H / (ey2 - ey1 + 1.0f);
    const float kx = (kxg - ex1) * sx;
    const float ky = (kyg - ey1) * sy;
    const bool valid = (vis != 0.0f) && (flag > 0);

    // ---- separable Gaussian tables: 64 expf per CTA (16x fewer than naive) ----
    if (tid < FEAT_W) {
        const float d = (float)tid + 0.5f - kx;
        exs[tid] = expf(-(d * d) / 5.12f);       // 2*SIGMA^2
    } else if (tid < FEAT_W + FEAT_H) {
        const int r = tid - FEAT_W;
        const float d = (float)r + 0.5f - ky;
        eys[r] = expf(-(d * d) / 5.12f);
    }
    __syncthreads();

    // ---- analytic 'has': peak of exs[gx]*eys[gy] at clamped-nearest cell ----
    int ixn = __float2int_rn(kx - 0.5f); ixn = min(FEAT_W - 1, max(0, ixn));
    int iyn = __float2int_rn(ky - 0.5f); iyn = min(FEAT_H - 1, max(0, iyn));
    const float smax = exs[ixn] * eys[iyn];
    const bool  has  = valid && (smax >= 0.6f);
    const float hasf = has ? 1.0f : 0.0f;

    // ---- this thread's 4 pixels: row gy, cols gx0..gx0+3 ----
    const int gy  = tid >> 3;
    const int gx0 = (tid & 7) << 2;
    const float ey   = eys[gy];
    const float offy = ky - (float)gy;
    const float4 exv = reinterpret_cast<const float4*>(exs)[tid & 7];
    const float exa[4] = {exv.x, exv.y, exv.z, exv.w};

    float cls[4], offx[4], m2f[4], m3f[4];
#pragma unroll
    for (int j = 0; j < 4; ++j) {
        const float gx = (float)(gx0 + j);
        const float sc = exa[j] * ey;
        offx[j] = kx - gx;
        m2f[j] = (valid && sc >= 0.6f) ? 1.0f : 0.0f;
        m3f[j] = (valid && sc >= 0.5f) ? 1.0f : 0.0f;   // depth thr == 3d thr
        cls[j] = has ? sc : -1.0f;                      // branchless (SELP)
    }

    // ---- 20 coalesced float4 stores, default .wb policy ----
    const long long pix  = (long long)tid * 4;
    const long long base = (long long)bn * HW + pix;
    const long long b2c  = (long long)bn * 2 * HW + pix;
    const long long b3c  = (long long)bn * 3 * HW + pix;

    st4(out + OFF_CLS  + base, cls[0], cls[1], cls[2], cls[3]);
    st4(out + OFF_CLSW + base, hasf, hasf, hasf, hasf);

    st4(out + OFF_R2  + b2c,      offx[0]*m2f[0], offx[1]*m2f[1], offx[2]*m2f[2], offx[3]*m2f[3]);
    st4(out + OFF_R2  + b2c + HW, offy*m2f[0],    offy*m2f[1],    offy*m2f[2],    offy*m2f[3]);
    st4(out + OFF_R2W + b2c,      m2f[0], m2f[1], m2f[2], m2f[3]);
    st4(out + OFF_R2W + b2c + HW, m2f[0], m2f[1], m2f[2], m2f[3]);

    st4(out + OFF_R3  + b2c,      offx[0]*m3f[0], offx[1]*m3f[1], offx[2]*m3f[2], offx[3]*m3f[3]);
    st4(out + OFF_R3  + b2c + HW, offy*m3f[0],    offy*m3f[1],    offy*m3f[2],    offy*m3f[3]);
    st4(out + OFF_R3W + b2c,      m3f[0], m3f[1], m3f[2], m3f[3]);
    st4(out + OFF_R3W + b2c + HW, m3f[0], m3f[1], m3f[2], m3f[3]);

    st4(out + OFF_DL  + base, depth*m3f[0], depth*m3f[1], depth*m3f[2], depth*m3f[3]);
    st4(out + OFF_DLW + base, m3f[0], m3f[1], m3f[2], m3f[3]);

    st4(out + OFF_DIM  + b3c,        dim0*m3f[0], dim0*m3f[1], dim0*m3f[2], dim0*m3f[3]);
    st4(out + OFF_DIM  + b3c + HW,   dim1*m3f[0], dim1*m3f[1], dim1*m3f[2], dim1*m3f[3]);
    st4(out + OFF_DIM  + b3c + 2*HW, dim2*m3f[0], dim2*m3f[1], dim2*m3f[2], dim2*m3f[3]);
    st4(out + OFF_DIMW + b3c,        m3f[0], m3f[1], m3f[2], m3f[3]);
    st4(out + OFF_DIMW + b3c + HW,   m3f[0], m3f[1], m3f[2], m3f[3]);
    st4(out + OFF_DIMW + b3c + 2*HW, m3f[0], m3f[1], m3f[2], m3f[3]);

    st4(out + OFF_ROT  + base, rot*m3f[0], rot*m3f[1], rot*m3f[2], rot*m3f[3]);
    st4(out + OFF_ROTW + base, m3f[0], m3f[1], m3f[2], m3f[3]);
}

extern "C" void kernel_launch(void* const* d_in, const int* in_sizes, int n_in,
                              void* d_out, int out_size) {
    const float* boxes          = (const float*)d_in[0];
    const float* gt_boxes       = (const float*)d_in[1];
    const int*   match_pos_flag = (const int*)d_in[2];
    const int*   match_gt_id    = (const int*)d_in[3];
    float* out = (float*)d_out;

    // One 256-thread CTA per box (measured optimum): 4096 CTAs, 4 KB
    // contiguous burst per channel per CTA, default .wb stores.
    rcnn3d_label_kernel<<<4096, 256>>>(boxes, gt_boxes, match_pos_flag,
                                       match_gt_id, out);
}